// round 7
// baseline (speedup 1.0000x reference)
#include <cuda_runtime.h>
#include <math.h>
#include <stdint.h>

#define NN 128
#define DD 2048
#define EPSF 1e-12f
#define MARGINF 0.3f
#define KCHUNK 32        // K per GEMM block
#define KP 16            // k-pairs per chunk
#define NKCH 64          // K chunks (64*32 = 2048)
#define NBLK 256         // two blocks per SM, all co-resident
#define S2 66            // smem row stride in float2

// ---------------- device scratch (no allocations allowed) ----------------
__device__ float g_part[NN * NKCH * NN];   // partials [i][kc][j], 4 MB
__device__ float g_norm[2 * NN];
__device__ float g_dist_ap[NN];
__device__ int   g_sel1[NN];
__device__ int   g_sel2[NN];
__device__ float g_trip[NN];
__device__ int   g_c0, g_c1, g_c2;         // phase barriers (zero-init, self-reset)

__device__ __forceinline__ void ffma2(unsigned long long& acc,
                                      unsigned long long a, unsigned long long b) {
    asm("fma.rn.f32x2 %0, %1, %2, %0;" : "+l"(acc) : "l"(a), "l"(b));
}
__device__ __forceinline__ float2 up2(unsigned long long v) {
    float2 r;
    asm("mov.b64 {%0, %1}, %2;" : "=f"(r.x), "=f"(r.y) : "l"(v));
    return r;
}

// grid-wide spin barrier (all NBLK blocks resident: 2 per SM)
__device__ __forceinline__ void gbar(int* c) {
    __threadfence();
    __syncthreads();
    if (threadIdx.x == 0) {
        atomicAdd(c, 1);
        while (*(volatile int*)c != NBLK) __nanosleep(32);
    }
    __syncthreads();
    __threadfence();
}

__global__ void __launch_bounds__(256, 2)
k_fused(const float* __restrict__ f1, const float* __restrict__ f2,
        const int* __restrict__ tgt, float* __restrict__ out, int out_size) {
    const int tid = threadIdx.x;
    const int bid = blockIdx.x;
    const int w = tid >> 5, lane = tid & 31;

    __shared__ float2 As2[KP][S2];   // As2[kp][row] = (A[2kp],A[2kp+1]) of row
    __shared__ float2 Bs2[KP][S2];
    __shared__ int    st[NN];
    __shared__ unsigned s_bal[4];
    __shared__ float  s_dot[2][NN];
    __shared__ float  nred[8];
    __shared__ float  s_ap[8];
    __shared__ unsigned long long s_k1[8], s_k2[8];
    __shared__ float  red[8][2];
    __shared__ int    s_last;

    // ================= Phase A: split-K GEMM + folded norms ================
    const int quad = bid >> 6;            // 0..3
    const int kc = bid & 63;              // K chunk
    const int i0 = (quad & 1) * 64;
    const int j0 = (quad >> 1) * 64;
    const int k0 = kc * KCHUNK;

    // GEMM tile loads: 64 rows x 32 K per matrix = 512 float4; 2 per thread
    float4 va[2], vb[2];
    int rw[2], k4[2];
    #pragma unroll
    for (int s = 0; s < 2; s++) {
        const int idx = tid + 256 * s;    // 0..511
        rw[s] = idx >> 3;                 // 0..63
        k4[s] = idx & 7;                  // float4 index within 32-wide K
        va[s] = *(const float4*)(f1 + (size_t)(i0 + rw[s]) * DD + k0 + k4[s] * 4);
        vb[s] = *(const float4*)(f2 + (size_t)(j0 + rw[s]) * DD + k0 + k4[s] * 4);
    }
    // norm row: exactly one row per block (256 blocks = 256 rows)
    const float4* nb = (const float4*)((bid < NN) ? (f1 + (size_t)bid * DD)
                                                  : (f2 + (size_t)(bid - NN) * DD));
    float4 n0 = nb[tid], n1 = nb[tid + 256];

    // stage GEMM tiles, k-pair interleaved
    #pragma unroll
    for (int s = 0; s < 2; s++) {
        As2[2 * k4[s] + 0][rw[s]] = make_float2(va[s].x, va[s].y);
        As2[2 * k4[s] + 1][rw[s]] = make_float2(va[s].z, va[s].w);
        Bs2[2 * k4[s] + 0][rw[s]] = make_float2(vb[s].x, vb[s].y);
        Bs2[2 * k4[s] + 1][rw[s]] = make_float2(vb[s].z, vb[s].w);
    }
    float ns = n0.x * n0.x + n0.y * n0.y + n0.z * n0.z + n0.w * n0.w
             + n1.x * n1.x + n1.y * n1.y + n1.z * n1.z + n1.w * n1.w;
    if (tid < NN) st[tid] = tgt[tid];
    __syncthreads();

    // 4x4 register tile; warp footprint = 4 (A) x 8 (B) distinct addresses
    const int ty4 = ((w >> 1) * 4 + (lane >> 3)) * 4;   // 16 row-groups
    const int tx4 = ((w & 1) * 8 + (lane & 7)) * 4;     // 16 col-groups

    unsigned long long acc[4][4];
    #pragma unroll
    for (int m = 0; m < 4; m++)
        #pragma unroll
        for (int n = 0; n < 4; n++) acc[m][n] = 0ull;

    #pragma unroll
    for (int kp = 0; kp < KP; kp++) {
        ulonglong2 a0 = *(const ulonglong2*)&As2[kp][ty4];
        ulonglong2 a1 = *(const ulonglong2*)&As2[kp][ty4 + 2];
        ulonglong2 b0 = *(const ulonglong2*)&Bs2[kp][tx4];
        ulonglong2 b1 = *(const ulonglong2*)&Bs2[kp][tx4 + 2];
        unsigned long long A[4] = {a0.x, a0.y, a1.x, a1.y};
        unsigned long long B[4] = {b0.x, b0.y, b1.x, b1.y};
        #pragma unroll
        for (int m = 0; m < 4; m++)
            #pragma unroll
            for (int n = 0; n < 4; n++)
                ffma2(acc[m][n], A[m], B[n]);
    }

    #pragma unroll
    for (int m = 0; m < 4; m++) {
        float v[4];
        #pragma unroll
        for (int n = 0; n < 4; n++) {
            float2 p = up2(acc[m][n]);
            v[n] = p.x + p.y;
        }
        *(float4*)&g_part[((size_t)(i0 + ty4 + m) * NKCH + kc) * NN + j0 + tx4] =
            make_float4(v[0], v[1], v[2], v[3]);
    }

    // norm reduce: whole block covers one row
    #pragma unroll
    for (int o = 16; o; o >>= 1) ns += __shfl_xor_sync(0xffffffffu, ns, o);
    if (lane == 0) nred[w] = ns;

    // ballot-based rank among negatives (only row-owner blocks need it)
    bool pos = false;
    int rank = 0;
    unsigned mybal = 0;
    if (bid < NN) {
        const int ti = st[bid];
        if (tid < NN) {
            pos = (st[tid] == ti);
            mybal = __ballot_sync(0xffffffffu, !pos);
            if (lane == 0) s_bal[w] = mybal;
        }
    }
    __syncthreads();
    if (tid == 0) {
        float s = 0.f;
        #pragma unroll
        for (int q = 0; q < 8; q++) s += nred[q];
        g_norm[bid] = s;
    }
    if (bid < NN && tid < NN) {
        #pragma unroll
        for (int q = 0; q < 4; q++) rank += (q < w) ? __popc(s_bal[q]) : 0;
        rank += __popc(mybal & ((1u << lane) - 1u));
    }

    gbar(&g_c0);

    // ================= Phase B: distances + hard-example selection ========
    if (bid < NN) {
        const int i = bid;
        const int j = tid & 127;
        const int kh = tid >> 7;           // 2 K-halves of 32 chunks each

        const float* pp = g_part + ((size_t)i * NKCH + kh * 32) * NN + j;
        float a0 = 0.f, a1 = 0.f, a2 = 0.f, a3 = 0.f;
        #pragma unroll
        for (int c = 0; c < 32; c += 4) {
            a0 += __ldcg(pp + (size_t)(c + 0) * NN);
            a1 += __ldcg(pp + (size_t)(c + 1) * NN);
            a2 += __ldcg(pp + (size_t)(c + 2) * NN);
            a3 += __ldcg(pp + (size_t)(c + 3) * NN);
        }
        s_dot[kh][j] = (a0 + a1) + (a2 + a3);
        __syncthreads();

        if (tid < NN) {
            float dot = s_dot[0][j] + s_dot[1][j];
            float d2 = __ldcg(&g_norm[i]) + __ldcg(&g_norm[NN + j]) - 2.f * dot;
            float d = sqrtf(fmaxf(d2, EPSF));

            float apv = pos ? d : -INFINITY;
            // (distance, column) lexicographic key: min == argmin with
            // first-occurrence tie-break (d > 0, float bits order-preserving)
            unsigned long long key =
                ((unsigned long long)__float_as_uint(d) << 32) | (unsigned)j;
            unsigned long long k1 = (!pos && rank < 56) ? key : ~0ull;
            unsigned long long k2 = (!pos && rank >= 56 && rank < 112) ? key : ~0ull;

            #pragma unroll
            for (int o = 16; o; o >>= 1) {
                apv = fmaxf(apv, __shfl_xor_sync(0xffffffffu, apv, o));
                unsigned long long t1 = __shfl_xor_sync(0xffffffffu, k1, o);
                unsigned long long t2 = __shfl_xor_sync(0xffffffffu, k2, o);
                k1 = (t1 < k1) ? t1 : k1;
                k2 = (t2 < k2) ? t2 : k2;
            }
            if (lane == 0) { s_ap[w] = apv; s_k1[w] = k1; s_k2[w] = k2; }
        }
        __syncthreads();
        if (tid == 0) {
            float ap = s_ap[0];
            unsigned long long m1 = s_k1[0], m2 = s_k2[0];
            #pragma unroll
            for (int q = 1; q < 4; q++) {
                ap = fmaxf(ap, s_ap[q]);
                if (s_k1[q] < m1) m1 = s_k1[q];
                if (s_k2[q] < m2) m2 = s_k2[q];
            }
            g_dist_ap[i] = ap;
            g_sel1[i] = (int)(m1 & 0xffffffffull);
            g_sel2[i] = (int)(m2 & 0xffffffffull);
        }
    }

    gbar(&g_c1);

    // ================= Phase C: dist_an + triplet ==========================
    if (bid < NN) {
        const int k = bid;
        // feat_rgb_mid / feat_ir_mid index shuffle; anchor is always f1[k]
        int m = (k < 32) ? k : (k < 64) ? (k + 32) : (k < 96) ? (k - 32) : k;
        const int a = __ldcg(&g_sel1[m]);
        const int b = __ldcg(&g_sel2[m]);

        const float4* xk = (const float4*)(f1 + (size_t)k * DD);
        const float4* xa = (const float4*)(f1 + (size_t)a * DD);
        const float4* xb = (const float4*)(f1 + (size_t)b * DD);

        float s1 = 0.f, ab = 0.f;
        #pragma unroll
        for (int s = 0; s < 2; s++) {
            const int t = tid + 256 * s;
            float4 vk = xk[t], v1 = xa[t], v2 = xb[t];
            float4 fm;
            fm.x = 0.5f * (v1.x + v2.x); fm.y = 0.5f * (v1.y + v2.y);
            fm.z = 0.5f * (v1.z + v2.z); fm.w = 0.5f * (v1.w + v2.w);
            s1 += vk.x * vk.x + vk.y * vk.y + vk.z * vk.z + vk.w * vk.w
                + fm.x * fm.x + fm.y * fm.y + fm.z * fm.z + fm.w * fm.w;
            ab += vk.x * fm.x + vk.y * fm.y + vk.z * fm.z + vk.w * fm.w;
        }
        #pragma unroll
        for (int o = 16; o; o >>= 1) {
            s1 += __shfl_xor_sync(0xffffffffu, s1, o);
            ab += __shfl_xor_sync(0xffffffffu, ab, o);
        }
        if (lane == 0) { red[w][0] = s1; red[w][1] = ab; }
        __syncthreads();
        if (tid == 0) {
            float t1 = 0.f, t2 = 0.f;
            #pragma unroll
            for (int q = 0; q < 8; q++) { t1 += red[q][0]; t2 += red[q][1]; }
            float d2 = t1 - 2.f * t2;
            float dan = sqrtf(fmaxf(d2, EPSF));
            g_trip[k] = __ldcg(&g_dist_ap[k]) - dan + MARGINF;
        }
    }

    // ================= finalize: last-arriving block (parallel) ============
    __threadfence();
    __syncthreads();
    if (tid == 0) {
        int done = atomicAdd(&g_c2, 1);
        s_last = (done == NBLK - 1) ? 1 : 0;
    }
    __syncthreads();
    if (s_last) {
        __threadfence();
        float t = (tid < NN) ? __ldcg(&g_trip[tid]) : 0.f;
        float v = (tid < NN && t > 0.f) ? t : 0.f;
        float c = (tid < NN && t > 0.f) ? 1.f : 0.f;
        #pragma unroll
        for (int o = 16; o; o >>= 1) {
            v += __shfl_xor_sync(0xffffffffu, v, o);
            c += __shfl_xor_sync(0xffffffffu, c, o);
        }
        if (lane == 0) { red[w][0] = v; red[w][1] = c; }
        __syncthreads();
        if (tid == 0) {
            float s = 0.f, cc = 0.f;
            #pragma unroll
            for (int q = 0; q < 4; q++) { s += red[q][0]; cc += red[q][1]; }
            out[0] = s * (1.0f / 128.0f);
            if (out_size > 1) out[1] = cc;
            // reset barriers for next graph replay
            g_c0 = 0; g_c1 = 0; g_c2 = 0;
        }
    }
}

// ---------------- launch ----------------
extern "C" void kernel_launch(void* const* d_in, const int* in_sizes, int n_in,
                              void* d_out, int out_size) {
    const float* f1 = (const float*)d_in[0];
    const float* f2 = (const float*)d_in[1];
    const int*   tgt = (const int*)d_in[2];
    (void)in_sizes; (void)n_in;

    k_fused<<<NBLK, 256>>>(f1, f2, tgt, (float*)d_out, out_size);
}

// round 8
// speedup vs baseline: 1.1552x; 1.1552x over previous
#include <cuda_runtime.h>
#include <math.h>
#include <stdint.h>

#define NN 128
#define DD 2048
#define EPSF 1e-12f
#define MARGINF 0.3f
#define KCHUNK 64        // K per GEMM block
#define KP 32            // k-pairs per chunk
#define NKCH 32          // K chunks (32*64 = 2048)
#define NBLK 128         // one block per SM, all co-resident
#define S2 66            // smem row stride in float2

// ---------------- device scratch (no allocations allowed) ----------------
__device__ float g_part[NN * NKCH * NN];   // partials [i][kc][j], 2 MB
__device__ float g_norm[2 * NN];
__device__ float g_ap[NN];                 // hardest-positive distance per row
__device__ float g_dan[NN];                // dist_an per anchor
__device__ int   g_c0, g_c2;               // phase barriers (zero-init, self-reset)

__device__ __forceinline__ void ffma2(unsigned long long& acc,
                                      unsigned long long a, unsigned long long b) {
    asm("fma.rn.f32x2 %0, %1, %2, %0;" : "+l"(acc) : "l"(a), "l"(b));
}
__device__ __forceinline__ float2 up2(unsigned long long v) {
    float2 r;
    asm("mov.b64 {%0, %1}, %2;" : "=f"(r.x), "=f"(r.y) : "l"(v));
    return r;
}

// grid-wide spin barrier (all NBLK blocks resident)
__device__ __forceinline__ void gbar(int* c) {
    __threadfence();
    __syncthreads();
    if (threadIdx.x == 0) {
        atomicAdd(c, 1);
        while (*(volatile int*)c != NBLK) __nanosleep(32);
    }
    __syncthreads();
    __threadfence();
}

__global__ void __launch_bounds__(256, 1)
k_fused(const float* __restrict__ f1, const float* __restrict__ f2,
        const int* __restrict__ tgt, float* __restrict__ out, int out_size) {
    const int tid = threadIdx.x;
    const int bid = blockIdx.x;
    const int w = tid >> 5, lane = tid & 31;

    __shared__ float2 As2[KP][S2];   // As2[kp][row] = (A[2kp],A[2kp+1]) of row
    __shared__ float2 Bs2[KP][S2];
    __shared__ int    st[NN];
    __shared__ unsigned s_bal[4];
    __shared__ float  s_dot[2][NN];
    __shared__ float  nred[8];
    __shared__ float  s_ap[8];
    __shared__ unsigned long long s_k1[8], s_k2[8];
    __shared__ int    s_sa, s_sb;
    __shared__ float  red[8][2];
    __shared__ int    s_last;

    // ================= Phase A: split-K GEMM + folded norms ================
    const int quad = bid >> 5;            // 0..3
    const int kc = bid & 31;
    const int i0 = (quad & 1) * 64;
    const int j0 = (quad >> 1) * 64;
    const int k0 = kc * KCHUNK;

    // GEMM tile loads: 64 rows x 64 K per matrix = 1024 float4; 4 per thread
    float4 va[4], vb[4];
    int rw[4], k4[4];
    #pragma unroll
    for (int s = 0; s < 4; s++) {
        const int idx = tid + 256 * s;    // 0..1023
        rw[s] = idx >> 4;                 // 0..63
        k4[s] = idx & 15;
        va[s] = *(const float4*)(f1 + (size_t)(i0 + rw[s]) * DD + k0 + k4[s] * 4);
        vb[s] = *(const float4*)(f2 + (size_t)(j0 + rw[s]) * DD + k0 + k4[s] * 4);
    }
    // norm rows 2*bid, 2*bid+1: 512 float4 per row, 4 per thread (coalesced)
    const int nrow = 2 * bid + (tid >> 7);
    const float4* nb = (const float4*)((nrow < NN) ? (f1 + (size_t)nrow * DD)
                                                   : (f2 + (size_t)(nrow - NN) * DD));
    float4 n0 = nb[(tid & 127)];
    float4 n1 = nb[(tid & 127) + 128];
    float4 n2 = nb[(tid & 127) + 256];
    float4 n3 = nb[(tid & 127) + 384];

    // stage GEMM tiles, k-pair interleaved
    #pragma unroll
    for (int s = 0; s < 4; s++) {
        As2[2 * k4[s] + 0][rw[s]] = make_float2(va[s].x, va[s].y);
        As2[2 * k4[s] + 1][rw[s]] = make_float2(va[s].z, va[s].w);
        Bs2[2 * k4[s] + 0][rw[s]] = make_float2(vb[s].x, vb[s].y);
        Bs2[2 * k4[s] + 1][rw[s]] = make_float2(vb[s].z, vb[s].w);
    }
    float ns = n0.x * n0.x + n0.y * n0.y + n0.z * n0.z + n0.w * n0.w
             + n1.x * n1.x + n1.y * n1.y + n1.z * n1.z + n1.w * n1.w
             + n2.x * n2.x + n2.y * n2.y + n2.z * n2.z + n2.w * n2.w
             + n3.x * n3.x + n3.y * n3.y + n3.z * n3.z + n3.w * n3.w;
    if (tid < NN) st[tid] = tgt[tid];
    __syncthreads();

    // 4x4 register tile; warp footprint = 4 (A) x 8 (B) distinct addresses
    const int ty4 = ((w >> 1) * 4 + (lane >> 3)) * 4;   // 16 row-groups
    const int tx4 = ((w & 1) * 8 + (lane & 7)) * 4;     // 16 col-groups

    unsigned long long acc[4][4];
    #pragma unroll
    for (int m = 0; m < 4; m++)
        #pragma unroll
        for (int n = 0; n < 4; n++) acc[m][n] = 0ull;

    #pragma unroll
    for (int kp = 0; kp < KP; kp++) {
        ulonglong2 a0 = *(const ulonglong2*)&As2[kp][ty4];
        ulonglong2 a1 = *(const ulonglong2*)&As2[kp][ty4 + 2];
        ulonglong2 b0 = *(const ulonglong2*)&Bs2[kp][tx4];
        ulonglong2 b1 = *(const ulonglong2*)&Bs2[kp][tx4 + 2];
        unsigned long long A[4] = {a0.x, a0.y, a1.x, a1.y};
        unsigned long long B[4] = {b0.x, b0.y, b1.x, b1.y};
        #pragma unroll
        for (int m = 0; m < 4; m++)
            #pragma unroll
            for (int n = 0; n < 4; n++)
                ffma2(acc[m][n], A[m], B[n]);
    }

    #pragma unroll
    for (int m = 0; m < 4; m++) {
        float v[4];
        #pragma unroll
        for (int n = 0; n < 4; n++) {
            float2 p = up2(acc[m][n]);
            v[n] = p.x + p.y;
        }
        *(float4*)&g_part[((size_t)(i0 + ty4 + m) * NKCH + kc) * NN + j0 + tx4] =
            make_float4(v[0], v[1], v[2], v[3]);
    }

    // norm reduce (each warp covers one row: tid>>7 constant within warp)
    #pragma unroll
    for (int o = 16; o; o >>= 1) ns += __shfl_xor_sync(0xffffffffu, ns, o);
    if (lane == 0) nred[w] = ns;

    // ballot-based rank among negatives (depends only on tgt)
    const int ti = st[bid];
    bool pos = false;
    unsigned mybal = 0;
    if (tid < NN) {
        pos = (st[tid] == ti);
        mybal = __ballot_sync(0xffffffffu, !pos);
        if (lane == 0) s_bal[w] = mybal;
    }
    __syncthreads();
    if (tid == 0)        g_norm[2 * bid]     = nred[0] + nred[1] + nred[2] + nred[3];
    else if (tid == 128) g_norm[2 * bid + 1] = nred[4] + nred[5] + nred[6] + nred[7];

    int rank = 0;
    if (tid < NN) {
        #pragma unroll
        for (int q = 0; q < 4; q++) rank += (q < w) ? __popc(s_bal[q]) : 0;
        rank += __popc(mybal & ((1u << lane) - 1u));
    }

    gbar(&g_c0);

    // ================= Phase B: distances + hard-example selection ========
    {
        const int i = bid;
        const int j = tid & 127;
        const int kh = tid >> 7;           // 2 K-halves of 16 chunks each

        const float* pp = g_part + ((size_t)i * NKCH + kh * 16) * NN + j;
        float a0 = 0.f, a1 = 0.f, a2 = 0.f, a3 = 0.f;
        #pragma unroll
        for (int c = 0; c < 16; c += 4) {
            a0 += __ldcg(pp + (size_t)(c + 0) * NN);
            a1 += __ldcg(pp + (size_t)(c + 1) * NN);
            a2 += __ldcg(pp + (size_t)(c + 2) * NN);
            a3 += __ldcg(pp + (size_t)(c + 3) * NN);
        }
        s_dot[kh][j] = (a0 + a1) + (a2 + a3);
        __syncthreads();

        if (tid < NN) {
            float dot = s_dot[0][j] + s_dot[1][j];
            float d2 = __ldcg(&g_norm[i]) + __ldcg(&g_norm[NN + j]) - 2.f * dot;
            float d = sqrtf(fmaxf(d2, EPSF));

            float apv = pos ? d : -INFINITY;
            // (distance, column) lexicographic key: min == argmin with
            // first-occurrence tie-break (d > 0, float bits order-preserving)
            unsigned long long key =
                ((unsigned long long)__float_as_uint(d) << 32) | (unsigned)j;
            unsigned long long k1 = (!pos && rank < 56) ? key : ~0ull;
            unsigned long long k2 = (!pos && rank >= 56 && rank < 112) ? key : ~0ull;

            #pragma unroll
            for (int o = 16; o; o >>= 1) {
                apv = fmaxf(apv, __shfl_xor_sync(0xffffffffu, apv, o));
                unsigned long long t1 = __shfl_xor_sync(0xffffffffu, k1, o);
                unsigned long long t2 = __shfl_xor_sync(0xffffffffu, k2, o);
                k1 = (t1 < k1) ? t1 : k1;
                k2 = (t2 < k2) ? t2 : k2;
            }
            if (lane == 0) { s_ap[w] = apv; s_k1[w] = k1; s_k2[w] = k2; }
        }
        __syncthreads();
        if (tid == 0) {
            float ap = s_ap[0];
            unsigned long long m1 = s_k1[0], m2 = s_k2[0];
            #pragma unroll
            for (int q = 1; q < 4; q++) {
                ap = fmaxf(ap, s_ap[q]);
                if (s_k1[q] < m1) m1 = s_k1[q];
                if (s_k2[q] < m2) m2 = s_k2[q];
            }
            g_ap[bid] = ap;
            s_sa = (int)(m1 & 0xffffffffull);
            s_sb = (int)(m2 & 0xffffffffull);
        }
        __syncthreads();
    }

    // ========== Phase C (no barrier!): dist_an for anchor k = inv(bid) =====
    // m(k) bijection: block i owns sel for mid-feature row i, which is used by
    // exactly one anchor: i<32 -> k=i; 32<=i<64 -> k=i+32; 64<=i<96 -> k=i-32;
    // i>=96 -> k=i. Anchor feature is always f1[k]; fm from this block's sel.
    {
        const int i = bid;
        const int k = (i < 32) ? i : (i < 64) ? (i + 32) : (i < 96) ? (i - 32) : i;
        const int a = s_sa;
        const int b = s_sb;

        const float4* xk = (const float4*)(f1 + (size_t)k * DD);
        const float4* xa = (const float4*)(f1 + (size_t)a * DD);
        const float4* xb = (const float4*)(f1 + (size_t)b * DD);

        float s1 = 0.f, ab = 0.f;
        #pragma unroll
        for (int s = 0; s < 2; s++) {
            const int t = tid + 256 * s;
            float4 vk = xk[t], v1 = xa[t], v2 = xb[t];
            float4 fm;
            fm.x = 0.5f * (v1.x + v2.x); fm.y = 0.5f * (v1.y + v2.y);
            fm.z = 0.5f * (v1.z + v2.z); fm.w = 0.5f * (v1.w + v2.w);
            s1 += vk.x * vk.x + vk.y * vk.y + vk.z * vk.z + vk.w * vk.w
                + fm.x * fm.x + fm.y * fm.y + fm.z * fm.z + fm.w * fm.w;
            ab += vk.x * fm.x + vk.y * fm.y + vk.z * fm.z + vk.w * fm.w;
        }
        #pragma unroll
        for (int o = 16; o; o >>= 1) {
            s1 += __shfl_xor_sync(0xffffffffu, s1, o);
            ab += __shfl_xor_sync(0xffffffffu, ab, o);
        }
        if (lane == 0) { red[w][0] = s1; red[w][1] = ab; }
        __syncthreads();
        if (tid == 0) {
            float t1 = 0.f, t2 = 0.f;
            #pragma unroll
            for (int q = 0; q < 8; q++) { t1 += red[q][0]; t2 += red[q][1]; }
            float d2 = t1 - 2.f * t2;
            g_dan[k] = sqrtf(fmaxf(d2, EPSF));
        }
    }

    // ================= finalize: last-arriving block (parallel) ============
    __threadfence();
    __syncthreads();
    if (tid == 0) {
        int done = atomicAdd(&g_c2, 1);
        s_last = (done == NBLK - 1) ? 1 : 0;
    }
    __syncthreads();
    if (s_last) {
        __threadfence();
        float t = 0.f;
        if (tid < NN)
            t = __ldcg(&g_ap[tid]) - __ldcg(&g_dan[tid]) + MARGINF;
        float v = (tid < NN && t > 0.f) ? t : 0.f;
        float c = (tid < NN && t > 0.f) ? 1.f : 0.f;
        #pragma unroll
        for (int o = 16; o; o >>= 1) {
            v += __shfl_xor_sync(0xffffffffu, v, o);
            c += __shfl_xor_sync(0xffffffffu, c, o);
        }
        if (lane == 0) { red[w][0] = v; red[w][1] = c; }
        __syncthreads();
        if (tid == 0) {
            float s = 0.f, cc = 0.f;
            #pragma unroll
            for (int q = 0; q < 4; q++) { s += red[q][0]; cc += red[q][1]; }
            out[0] = s * (1.0f / 128.0f);
            if (out_size > 1) out[1] = cc;
            // reset barriers for next graph replay
            g_c0 = 0; g_c2 = 0;
        }
    }
}

// ---------------- launch ----------------
extern "C" void kernel_launch(void* const* d_in, const int* in_sizes, int n_in,
                              void* d_out, int out_size) {
    const float* f1 = (const float*)d_in[0];
    const float* f2 = (const float*)d_in[1];
    const int*   tgt = (const int*)d_in[2];
    (void)in_sizes; (void)n_in;

    k_fused<<<NBLK, 256>>>(f1, f2, tgt, (float*)d_out, out_size);
}